// round 8
// baseline (speedup 1.0000x reference)
#include <cuda_runtime.h>
#include <cuda_fp16.h>
#include <cstdint>

#define HID   2048
#define INTER 10944
#define INTP  11008          // padded: 86*128
#define TTOK  4096
#define EPS   1e-6f

#define BK 64                // fp16 elems per k-chunk = 128B swizzled row
#define NSTAGE 3

// ---- kernel A: BM=128, BN=256 ----
#define A_BY   (128*128)                 // 16 KB
#define B_BY   (256*128)                 // 32 KB
#define STAGE_A (A_BY + B_BY)            // 48 KB
#define SMEM_A (NSTAGE*STAGE_A)          // 144 KB

// ---- kernel B (fused gate/up): BM=128, BN=128 (x2 weights) ----
#define FA_BY  (128*128)
#define FB_BY  (128*128)
#define STAGE_F (FA_BY + 2*FB_BY)        // 48 KB
#define SMEM_F (NSTAGE*STAGE_F)          // 144 KB

// ---------------- scratch ----------------
__device__ __half g_xn[(size_t)TTOK * HID];
__device__ __half g_q[(size_t)TTOK * HID];
__device__ float  g_hidden[(size_t)TTOK * HID];
__device__ __half g_act[(size_t)TTOK * INTP];
__device__ __half g_wq[(size_t)HID * HID];
__device__ __half g_wo[(size_t)HID * HID];
__device__ __half g_wg[(size_t)INTP * HID];
__device__ __half g_wu[(size_t)INTP * HID];
__device__ __half g_wd[(size_t)HID * INTP];

// ---------------- PTX helpers ----------------
__device__ __forceinline__ uint32_t smem_u32(const void* p) {
    uint32_t a;
    asm("{ .reg .u64 t; cvta.to.shared.u64 t, %1; cvt.u32.u64 %0, t; }" : "=r"(a) : "l"(p));
    return a;
}
#define SWZ(off) ((off) ^ (((off) >> 3) & 0x70))

__device__ __forceinline__ void cp16(uint32_t smem_dst, const void* gsrc) {
    asm volatile("cp.async.cg.shared.global [%0], [%1], 16;" :: "r"(smem_dst), "l"(gsrc));
}
#define CP_COMMIT  asm volatile("cp.async.commit_group;" ::: "memory")
#define CP_WAIT(n) asm volatile("cp.async.wait_group %0;" :: "n"(n) : "memory")

__device__ __forceinline__ void ldsm_x4(uint32_t r[4], uint32_t saddr) {
    asm volatile("ldmatrix.sync.aligned.m8n8.x4.shared.b16 {%0,%1,%2,%3}, [%4];"
        : "=r"(r[0]), "=r"(r[1]), "=r"(r[2]), "=r"(r[3]) : "r"(saddr));
}

__device__ __forceinline__ void mma16816(float c[4], const uint32_t a[4],
                                         uint32_t b0, uint32_t b1) {
    asm volatile(
        "mma.sync.aligned.m16n8k16.row.col.f32.f16.f16.f32 "
        "{%0,%1,%2,%3}, {%4,%5,%6,%7}, {%8,%9}, {%0,%1,%2,%3};"
        : "+f"(c[0]), "+f"(c[1]), "+f"(c[2]), "+f"(c[3])
        : "r"(a[0]), "r"(a[1]), "r"(a[2]), "r"(a[3]), "r"(b0), "r"(b1));
}

// ================= kernel A: C[M,N] = A[M,K] @ B[N,K]^T =================
// warp tile 64x64, warps 2(M) x 4(N).
// EPI 0: fp16 -> Ch.   EPI 1: fp32 acc + Res -> Cf.
template <int EPI>
__global__ void __launch_bounds__(256, 1)
gemm_w64(const __half* __restrict__ A, const __half* __restrict__ B,
         const float* __restrict__ Res, __half* __restrict__ Ch,
         float* __restrict__ Cf, int K, int N) {
    extern __shared__ char smem[];
    const uint32_t sb = smem_u32(smem);
    const int tid = threadIdx.x, warp = tid >> 5, lane = tid & 31;
    const int wm = warp & 1, wn = warp >> 1;
    const int m0 = blockIdx.x * 128, n0 = blockIdx.y * 256;
    const int nkb = K / BK;

    const __half* Ag = A + (size_t)m0 * K;
    const __half* Bg = B + (size_t)n0 * K;
    auto issue = [&](int kb) {
        const uint32_t base = sb + (kb % NSTAGE) * STAGE_A;
        const int koff = kb * BK;
        #pragma unroll
        for (int i = 0; i < 12; i++) {
            const int c = tid + i * 256;
            if (c < 1024) {
                const int r = c >> 3, cc = c & 7;
                cp16(base + SWZ((uint32_t)(r * 128 + cc * 16)),
                     Ag + (size_t)r * K + koff + cc * 8);
            } else {
                const int idx = c - 1024, r = idx >> 3, cc = idx & 7;
                cp16(base + A_BY + SWZ((uint32_t)(r * 128 + cc * 16)),
                     Bg + (size_t)r * K + koff + cc * 8);
            }
        }
    };

    const int frow = (lane & 7) | (((lane >> 3) & 1) << 3);
    const int fg = lane >> 4, fx = frow & 7;
    uint32_t arow[4], brow[4];
    #pragma unroll
    for (int mi = 0; mi < 4; mi++) arow[mi] = (uint32_t)((wm * 64 + mi * 16 + frow) * 128);
    #pragma unroll
    for (int nj = 0; nj < 4; nj++) brow[nj] = (uint32_t)(A_BY + (wn * 64 + nj * 16 + frow) * 128);

    float acc[4][8][4];
    #pragma unroll
    for (int mi = 0; mi < 4; mi++)
        #pragma unroll
        for (int j = 0; j < 8; j++)
            #pragma unroll
            for (int r = 0; r < 4; r++) acc[mi][j][r] = 0.0f;

    issue(0); CP_COMMIT;
    issue(1); CP_COMMIT;

    for (int kb = 0; kb < nkb; ++kb) {
        if (kb + 1 < nkb) CP_WAIT(1); else CP_WAIT(0);
        __syncthreads();
        if (kb + 2 < nkb) { issue(kb + 2); CP_COMMIT; }

        const uint32_t base = sb + (kb % NSTAGE) * STAGE_A;
        #pragma unroll
        for (int ks = 0; ks < 4; ks++) {
            const uint32_t colx = (uint32_t)(((2 * ks + fg) ^ fx) << 4);
            uint32_t a[4][4], b[4][4];
            #pragma unroll
            for (int mi = 0; mi < 4; mi++) ldsm_x4(a[mi], base + arow[mi] + colx);
            #pragma unroll
            for (int nj = 0; nj < 4; nj++) ldsm_x4(b[nj], base + brow[nj] + colx);
            #pragma unroll
            for (int mi = 0; mi < 4; mi++)
                #pragma unroll
                for (int nj = 0; nj < 4; nj++) {
                    mma16816(acc[mi][2 * nj + 0], a[mi], b[nj][0], b[nj][2]);
                    mma16816(acc[mi][2 * nj + 1], a[mi], b[nj][1], b[nj][3]);
                }
        }
    }

    const int rb = m0 + wm * 64 + (lane >> 2);
    const int cb = n0 + wn * 64 + (lane & 3) * 2;
    #pragma unroll
    for (int mi = 0; mi < 4; mi++) {
        #pragma unroll
        for (int j = 0; j < 8; j++) {
            const int r0 = rb + mi * 16;
            const int c  = cb + j * 8;
            if (EPI == 0) {
                *(__half2*)(Ch + (size_t)r0 * N + c) =
                    __floats2half2_rn(acc[mi][j][0], acc[mi][j][1]);
                *(__half2*)(Ch + (size_t)(r0 + 8) * N + c) =
                    __floats2half2_rn(acc[mi][j][2], acc[mi][j][3]);
            } else {
                float2 v0 = *(const float2*)(Res + (size_t)r0 * N + c);
                float2 v1 = *(const float2*)(Res + (size_t)(r0 + 8) * N + c);
                v0.x += acc[mi][j][0]; v0.y += acc[mi][j][1];
                v1.x += acc[mi][j][2]; v1.y += acc[mi][j][3];
                *(float2*)(Cf + (size_t)r0 * N + c)       = v0;
                *(float2*)(Cf + (size_t)(r0 + 8) * N + c) = v1;
            }
        }
    }
}

// ======= kernel B: fused gate/up + silu.  act = silu(A@Wg^T) * (A@Wu^T) =======
// BM=128, BN=128 (same n-range of both weights), warps 2x4, warp tile 64x32 (x2).
__global__ void __launch_bounds__(256, 1)
gemm_gateup(const __half* __restrict__ A, const __half* __restrict__ Wg,
            const __half* __restrict__ Wu, __half* __restrict__ act, int K) {
    extern __shared__ char smem[];
    const uint32_t sb = smem_u32(smem);
    const int tid = threadIdx.x, warp = tid >> 5, lane = tid & 31;
    const int wm = warp & 1, wn = warp >> 1;
    const int m0 = blockIdx.x * 128, n0 = blockIdx.y * 128;
    const int nkb = K / BK;

    const __half* Ag = A  + (size_t)m0 * K;
    const __half* Gg = Wg + (size_t)n0 * K;
    const __half* Ug = Wu + (size_t)n0 * K;
    auto issue = [&](int kb) {
        const uint32_t base = sb + (kb % NSTAGE) * STAGE_F;
        const int koff = kb * BK;
        #pragma unroll
        for (int i = 0; i < 12; i++) {
            const int c = tid + i * 256;
            const int idx = c & 1023, r = idx >> 3, cc = idx & 7;
            const uint32_t so = SWZ((uint32_t)(r * 128 + cc * 16));
            const size_t go = (size_t)r * K + koff + cc * 8;
            if (c < 1024)      cp16(base + so,             Ag + go);
            else if (c < 2048) cp16(base + FA_BY + so,     Gg + go);
            else               cp16(base + 2 * FA_BY + so, Ug + go);
        }
    };

    const int frow = (lane & 7) | (((lane >> 3) & 1) << 3);
    const int fg = lane >> 4, fx = frow & 7;
    uint32_t arow[4], grow[2], urow[2];
    #pragma unroll
    for (int mi = 0; mi < 4; mi++) arow[mi] = (uint32_t)((wm * 64 + mi * 16 + frow) * 128);
    #pragma unroll
    for (int nj = 0; nj < 2; nj++) {
        grow[nj] = (uint32_t)(FA_BY     + (wn * 32 + nj * 16 + frow) * 128);
        urow[nj] = (uint32_t)(2 * FA_BY + (wn * 32 + nj * 16 + frow) * 128);
    }

    float ag[4][4][4], au[4][4][4];
    #pragma unroll
    for (int mi = 0; mi < 4; mi++)
        #pragma unroll
        for (int j = 0; j < 4; j++)
            #pragma unroll
            for (int r = 0; r < 4; r++) { ag[mi][j][r] = 0.0f; au[mi][j][r] = 0.0f; }

    issue(0); CP_COMMIT;
    issue(1); CP_COMMIT;

    for (int kb = 0; kb < nkb; ++kb) {
        if (kb + 1 < nkb) CP_WAIT(1); else CP_WAIT(0);
        __syncthreads();
        if (kb + 2 < nkb) { issue(kb + 2); CP_COMMIT; }

        const uint32_t base = sb + (kb % NSTAGE) * STAGE_F;
        #pragma unroll
        for (int ks = 0; ks < 4; ks++) {
            const uint32_t colx = (uint32_t)(((2 * ks + fg) ^ fx) << 4);
            uint32_t a[4][4], bg[2][4], bu[2][4];
            #pragma unroll
            for (int mi = 0; mi < 4; mi++) ldsm_x4(a[mi], base + arow[mi] + colx);
            #pragma unroll
            for (int nj = 0; nj < 2; nj++) {
                ldsm_x4(bg[nj], base + grow[nj] + colx);
                ldsm_x4(bu[nj], base + urow[nj] + colx);
            }
            #pragma unroll
            for (int mi = 0; mi < 4; mi++)
                #pragma unroll
                for (int nj = 0; nj < 2; nj++) {
                    mma16816(ag[mi][2 * nj + 0], a[mi], bg[nj][0], bg[nj][2]);
                    mma16816(ag[mi][2 * nj + 1], a[mi], bg[nj][1], bg[nj][3]);
                    mma16816(au[mi][2 * nj + 0], a[mi], bu[nj][0], bu[nj][2]);
                    mma16816(au[mi][2 * nj + 1], a[mi], bu[nj][1], bu[nj][3]);
                }
        }
    }

    const int rb = m0 + wm * 64 + (lane >> 2);
    const int cb = n0 + wn * 32 + (lane & 3) * 2;
    #pragma unroll
    for (int mi = 0; mi < 4; mi++) {
        #pragma unroll
        for (int j = 0; j < 4; j++) {
            const int r0 = rb + mi * 16;
            const int c  = cb + j * 8;
            float g0 = ag[mi][j][0], g1 = ag[mi][j][1], g2 = ag[mi][j][2], g3 = ag[mi][j][3];
            float v0 = g0 / (1.0f + __expf(-g0)) * au[mi][j][0];
            float v1 = g1 / (1.0f + __expf(-g1)) * au[mi][j][1];
            float v2 = g2 / (1.0f + __expf(-g2)) * au[mi][j][2];
            float v3 = g3 / (1.0f + __expf(-g3)) * au[mi][j][3];
            *(__half2*)(act + (size_t)r0 * INTP + c)       = __floats2half2_rn(v0, v1);
            *(__half2*)(act + (size_t)(r0 + 8) * INTP + c) = __floats2half2_rn(v2, v3);
        }
    }
}

// ---------------- fp32 -> fp16 weight convert with padding ----------------
__global__ void cvt_pad(const float* __restrict__ in, __half* __restrict__ out,
                        int ro, int co, int ri, int ci) {
    const size_t i = (size_t)blockIdx.x * blockDim.x + threadIdx.x;
    const size_t n4 = ((size_t)ro * co) >> 2;
    if (i >= n4) return;
    const int cw = co >> 2;
    const int r = (int)(i / cw);
    const int c = (int)(i - (size_t)r * cw) * 4;
    __half2 h0 = __floats2half2_rn(0.f, 0.f), h1 = h0;
    if (r < ri && c < ci) {
        float4 v = *(const float4*)(in + (size_t)r * ci + c);
        h0 = __floats2half2_rn(v.x, v.y);
        h1 = __floats2half2_rn(v.z, v.w);
    }
    __half2* d = (__half2*)(out + (size_t)r * co + c);
    d[0] = h0; d[1] = h1;
}

// ---------------- rmsnorm -> fp16 ----------------
__global__ void rmsnorm_h(const float* __restrict__ x, const float* __restrict__ w,
                          __half* __restrict__ out) {
    const int row = blockIdx.x, t = threadIdx.x;
    const float4* xv = (const float4*)(x + (size_t)row * HID);
    const float4* wv = (const float4*)w;
    float4 a = xv[t], b = xv[t + 256];
    float ss = a.x*a.x + a.y*a.y + a.z*a.z + a.w*a.w
             + b.x*b.x + b.y*b.y + b.z*b.z + b.w*b.w;
    __shared__ float red[8];
    #pragma unroll
    for (int o = 16; o; o >>= 1) ss += __shfl_xor_sync(0xffffffffu, ss, o);
    if ((t & 31) == 0) red[t >> 5] = ss;
    __syncthreads();
    float tot = red[0]+red[1]+red[2]+red[3]+red[4]+red[5]+red[6]+red[7];
    const float sc = rsqrtf(tot * (1.0f / HID) + EPS);
    float4 wa = wv[t], wb = wv[t + 256];
    __half2* ov = (__half2*)(out + (size_t)row * HID);
    ov[2*t]   = __floats2half2_rn(a.x*sc*wa.x, a.y*sc*wa.y);
    ov[2*t+1] = __floats2half2_rn(a.z*sc*wa.z, a.w*sc*wa.w);
    ov[2*(t+256)]   = __floats2half2_rn(b.x*sc*wb.x, b.y*sc*wb.y);
    ov[2*(t+256)+1] = __floats2half2_rn(b.z*sc*wb.z, b.w*sc*wb.w);
}

// ---------------- launcher ----------------
extern "C" void kernel_launch(void* const* d_in, const int* in_sizes, int n_in,
                              void* d_out, int out_size) {
    const float* x      = (const float*)d_in[0];
    const float* in_w   = (const float*)d_in[2];
    const float* post_w = (const float*)d_in[3];
    const float* Wq     = (const float*)d_in[4];
    const float* Wo     = (const float*)d_in[5];
    const float* Wg     = (const float*)d_in[6];
    const float* Wu     = (const float*)d_in[7];
    const float* Wd     = (const float*)d_in[8];
    float* out = (float*)d_out;
    const int T = in_sizes[0] / HID;  // 4096

    __half *xn, *q, *act, *wq, *wo, *wg, *wu, *wd;
    float* hidden;
    cudaGetSymbolAddress((void**)&xn, g_xn);
    cudaGetSymbolAddress((void**)&q, g_q);
    cudaGetSymbolAddress((void**)&hidden, g_hidden);
    cudaGetSymbolAddress((void**)&act, g_act);
    cudaGetSymbolAddress((void**)&wq, g_wq);
    cudaGetSymbolAddress((void**)&wo, g_wo);
    cudaGetSymbolAddress((void**)&wg, g_wg);
    cudaGetSymbolAddress((void**)&wu, g_wu);
    cudaGetSymbolAddress((void**)&wd, g_wd);

    cudaFuncSetAttribute(gemm_w64<0>, cudaFuncAttributeMaxDynamicSharedMemorySize, SMEM_A);
    cudaFuncSetAttribute(gemm_w64<1>, cudaFuncAttributeMaxDynamicSharedMemorySize, SMEM_A);
    cudaFuncSetAttribute(gemm_gateup, cudaFuncAttributeMaxDynamicSharedMemorySize, SMEM_F);

    // weight conversion (fp32 -> fp16, padded for INTER)
    {
        auto launch_cvt = [&](const float* src, __half* dst, int ro, int co, int ri, int ci) {
            size_t n4 = ((size_t)ro * co) >> 2;
            cvt_pad<<<(unsigned)((n4 + 255) / 256), 256>>>(src, dst, ro, co, ri, ci);
        };
        launch_cvt(Wq, wq, HID, HID, HID, HID);
        launch_cvt(Wo, wo, HID, HID, HID, HID);
        launch_cvt(Wg, wg, INTP, HID, INTER, HID);
        launch_cvt(Wu, wu, INTP, HID, INTER, HID);
        launch_cvt(Wd, wd, HID, INTP, HID, INTER);
    }

    const dim3 gridH(T / 128, HID / 256);    // (32, 8)
    const dim3 gridF(T / 128, INTP / 128);   // (32, 86)

    // 1. input_layernorm -> fp16
    rmsnorm_h<<<T, 256>>>(x, in_w, xn);
    // 2. q = xn @ Wq^T (fp16)
    gemm_w64<0><<<gridH, 256, SMEM_A>>>(xn, wq, nullptr, q, nullptr, HID, HID);
    // 3. hidden = x + q @ Wo^T (fp32)
    gemm_w64<1><<<gridH, 256, SMEM_A>>>(q, wo, x, nullptr, hidden, HID, HID);
    // 4. post_attention_layernorm -> fp16
    rmsnorm_h<<<T, 256>>>(hidden, post_w, xn);
    // 5. act = silu(xn@Wg^T) * (xn@Wu^T)   (fused, fp16, padded N)
    gemm_gateup<<<gridF, 256, SMEM_F>>>(xn, wg, wu, act, HID);
    // 6. out = hidden + act @ Wd^T (fp32)
    gemm_w64<1><<<gridH, 256, SMEM_A>>>(act, wd, hidden, nullptr, out, INTP, HID);
}

// round 9
// speedup vs baseline: 1.0680x; 1.0680x over previous
#include <cuda_runtime.h>
#include <cuda_fp16.h>
#include <cstdint>

#define HID   2048
#define INTER 10944
#define INTP  11008          // padded: 86*128, 172*64
#define TTOK  4096
#define EPS   1e-6f

#define BK 64                // fp16 elems per k-chunk = 128B swizzled row
#define NSTAGE 3

// ---- kernel A (q/o/down): BM=128, BN=128, 128 threads (2x2 warps, 64x64 tiles) ----
#define A_BY   (128*128)                 // 16 KB
#define B_BY   (128*128)                 // 16 KB
#define STAGE_A (A_BY + B_BY)            // 32 KB
#define SMEM_A (NSTAGE*STAGE_A)          // 96 KB -> 2 CTAs/SM

// ---- kernel B (fused gate/up): BM=128, BN=64 per weight ----
#define FA_BY  (128*128)                 // 16 KB
#define FB_BY  (64*128)                  // 8 KB each weight
#define STAGE_F (FA_BY + 2*FB_BY)        // 32 KB
#define SMEM_F (NSTAGE*STAGE_F)          // 96 KB -> 2 CTAs/SM

// ---------------- scratch ----------------
__device__ __half g_xn[(size_t)TTOK * HID];
__device__ __half g_q[(size_t)TTOK * HID];
__device__ float  g_hidden[(size_t)TTOK * HID];
__device__ __half g_act[(size_t)TTOK * INTP];
__device__ __half g_wq[(size_t)HID * HID];
__device__ __half g_wo[(size_t)HID * HID];
__device__ __half g_wg[(size_t)INTP * HID];
__device__ __half g_wu[(size_t)INTP * HID];
__device__ __half g_wd[(size_t)HID * INTP];

// ---------------- PTX helpers ----------------
__device__ __forceinline__ uint32_t smem_u32(const void* p) {
    uint32_t a;
    asm("{ .reg .u64 t; cvta.to.shared.u64 t, %1; cvt.u32.u64 %0, t; }" : "=r"(a) : "l"(p));
    return a;
}
#define SWZ(off) ((off) ^ (((off) >> 3) & 0x70))

__device__ __forceinline__ void cp16(uint32_t smem_dst, const void* gsrc) {
    asm volatile("cp.async.cg.shared.global [%0], [%1], 16;" :: "r"(smem_dst), "l"(gsrc));
}
#define CP_COMMIT  asm volatile("cp.async.commit_group;" ::: "memory")
#define CP_WAIT(n) asm volatile("cp.async.wait_group %0;" :: "n"(n) : "memory")

__device__ __forceinline__ void ldsm_x4(uint32_t r[4], uint32_t saddr) {
    asm volatile("ldmatrix.sync.aligned.m8n8.x4.shared.b16 {%0,%1,%2,%3}, [%4];"
        : "=r"(r[0]), "=r"(r[1]), "=r"(r[2]), "=r"(r[3]) : "r"(saddr));
}

__device__ __forceinline__ void mma16816(float c[4], const uint32_t a[4],
                                         uint32_t b0, uint32_t b1) {
    asm volatile(
        "mma.sync.aligned.m16n8k16.row.col.f32.f16.f16.f32 "
        "{%0,%1,%2,%3}, {%4,%5,%6,%7}, {%8,%9}, {%0,%1,%2,%3};"
        : "+f"(c[0]), "+f"(c[1]), "+f"(c[2]), "+f"(c[3])
        : "r"(a[0]), "r"(a[1]), "r"(a[2]), "r"(a[3]), "r"(b0), "r"(b1));
}

// ================= kernel A: C[M,N] = A[M,K] @ B[N,K]^T =================
// 128 threads, warps 2(M) x 2(N), warp tile 64x64, 2 CTAs/SM.
// EPI 0: fp16 -> Ch.   EPI 1: fp32 acc + Res -> Cf.
template <int EPI>
__global__ void __launch_bounds__(128, 2)
gemm_qod(const __half* __restrict__ A, const __half* __restrict__ B,
         const float* __restrict__ Res, __half* __restrict__ Ch,
         float* __restrict__ Cf, int K, int N) {
    extern __shared__ char smem[];
    const uint32_t sb = smem_u32(smem);
    const int tid = threadIdx.x, warp = tid >> 5, lane = tid & 31;
    const int wm = warp & 1, wn = warp >> 1;
    const int m0 = blockIdx.x * 128, n0 = blockIdx.y * 128;
    const int nkb = K / BK;

    const __half* Ag = A + (size_t)m0 * K;
    const __half* Bg = B + (size_t)n0 * K;
    auto issue = [&](int kb) {
        const uint32_t base = sb + (kb % NSTAGE) * STAGE_A;
        const int koff = kb * BK;
        #pragma unroll
        for (int i = 0; i < 16; i++) {
            const int c = tid + i * 128;
            const int idx = c & 1023, r = idx >> 3, cc = idx & 7;
            const uint32_t so = SWZ((uint32_t)(r * 128 + cc * 16));
            const size_t go = (size_t)r * K + koff + cc * 8;
            if (c < 1024) cp16(base + so,         Ag + go);
            else          cp16(base + A_BY + so,  Bg + go);
        }
    };

    const int frow = (lane & 7) | (((lane >> 3) & 1) << 3);
    const int fg = lane >> 4, fx = frow & 7;
    uint32_t arow[4], brow[4];
    #pragma unroll
    for (int mi = 0; mi < 4; mi++) arow[mi] = (uint32_t)((wm * 64 + mi * 16 + frow) * 128);
    #pragma unroll
    for (int nj = 0; nj < 4; nj++) brow[nj] = (uint32_t)(A_BY + (wn * 64 + nj * 16 + frow) * 128);

    float acc[4][8][4];
    #pragma unroll
    for (int mi = 0; mi < 4; mi++)
        #pragma unroll
        for (int j = 0; j < 8; j++)
            #pragma unroll
            for (int r = 0; r < 4; r++) acc[mi][j][r] = 0.0f;

    issue(0); CP_COMMIT;
    issue(1); CP_COMMIT;

    for (int kb = 0; kb < nkb; ++kb) {
        if (kb + 1 < nkb) CP_WAIT(1); else CP_WAIT(0);
        __syncthreads();
        if (kb + 2 < nkb) { issue(kb + 2); CP_COMMIT; }

        const uint32_t base = sb + (kb % NSTAGE) * STAGE_A;
        #pragma unroll
        for (int ks = 0; ks < 4; ks++) {
            const uint32_t colx = (uint32_t)(((2 * ks + fg) ^ fx) << 4);
            uint32_t a[4][4], b[4][4];
            #pragma unroll
            for (int mi = 0; mi < 4; mi++) ldsm_x4(a[mi], base + arow[mi] + colx);
            #pragma unroll
            for (int nj = 0; nj < 4; nj++) ldsm_x4(b[nj], base + brow[nj] + colx);
            #pragma unroll
            for (int mi = 0; mi < 4; mi++)
                #pragma unroll
                for (int nj = 0; nj < 4; nj++) {
                    mma16816(acc[mi][2 * nj + 0], a[mi], b[nj][0], b[nj][2]);
                    mma16816(acc[mi][2 * nj + 1], a[mi], b[nj][1], b[nj][3]);
                }
        }
    }

    const int rb = m0 + wm * 64 + (lane >> 2);
    const int cb = n0 + wn * 64 + (lane & 3) * 2;
    #pragma unroll
    for (int mi = 0; mi < 4; mi++) {
        #pragma unroll
        for (int j = 0; j < 8; j++) {
            const int r0 = rb + mi * 16;
            const int c  = cb + j * 8;
            if (EPI == 0) {
                *(__half2*)(Ch + (size_t)r0 * N + c) =
                    __floats2half2_rn(acc[mi][j][0], acc[mi][j][1]);
                *(__half2*)(Ch + (size_t)(r0 + 8) * N + c) =
                    __floats2half2_rn(acc[mi][j][2], acc[mi][j][3]);
            } else {
                float2 v0 = *(const float2*)(Res + (size_t)r0 * N + c);
                float2 v1 = *(const float2*)(Res + (size_t)(r0 + 8) * N + c);
                v0.x += acc[mi][j][0]; v0.y += acc[mi][j][1];
                v1.x += acc[mi][j][2]; v1.y += acc[mi][j][3];
                *(float2*)(Cf + (size_t)r0 * N + c)       = v0;
                *(float2*)(Cf + (size_t)(r0 + 8) * N + c) = v1;
            }
        }
    }
}

// ======= kernel B: fused gate/up + silu.  act = silu(A@Wg^T) * (A@Wu^T) =======
// 128 threads, warps 2x2, BN=64 per weight, warp tile 64x32 per weight, 2 CTAs/SM.
__global__ void __launch_bounds__(128, 2)
gemm_gateup(const __half* __restrict__ A, const __half* __restrict__ Wg,
            const __half* __restrict__ Wu, __half* __restrict__ act, int K) {
    extern __shared__ char smem[];
    const uint32_t sb = smem_u32(smem);
    const int tid = threadIdx.x, warp = tid >> 5, lane = tid & 31;
    const int wm = warp & 1, wn = warp >> 1;
    const int m0 = blockIdx.x * 128, n0 = blockIdx.y * 64;
    const int nkb = K / BK;

    const __half* Ag = A  + (size_t)m0 * K;
    const __half* Gg = Wg + (size_t)n0 * K;
    const __half* Ug = Wu + (size_t)n0 * K;
    auto issue = [&](int kb) {
        const uint32_t base = sb + (kb % NSTAGE) * STAGE_F;
        const int koff = kb * BK;
        #pragma unroll
        for (int i = 0; i < 16; i++) {
            const int c = tid + i * 128;
            if (c < 1024) {
                const int r = c >> 3, cc = c & 7;
                cp16(base + SWZ((uint32_t)(r * 128 + cc * 16)),
                     Ag + (size_t)r * K + koff + cc * 8);
            } else if (c < 1536) {
                const int idx = c - 1024, r = idx >> 3, cc = idx & 7;
                cp16(base + FA_BY + SWZ((uint32_t)(r * 128 + cc * 16)),
                     Gg + (size_t)r * K + koff + cc * 8);
            } else {
                const int idx = c - 1536, r = idx >> 3, cc = idx & 7;
                cp16(base + FA_BY + FB_BY + SWZ((uint32_t)(r * 128 + cc * 16)),
                     Ug + (size_t)r * K + koff + cc * 8);
            }
        }
    };

    const int frow = (lane & 7) | (((lane >> 3) & 1) << 3);
    const int fg = lane >> 4, fx = frow & 7;
    uint32_t arow[4], grow[2], urow[2];
    #pragma unroll
    for (int mi = 0; mi < 4; mi++) arow[mi] = (uint32_t)((wm * 64 + mi * 16 + frow) * 128);
    #pragma unroll
    for (int nj = 0; nj < 2; nj++) {
        grow[nj] = (uint32_t)(FA_BY         + (wn * 32 + nj * 16 + frow) * 128);
        urow[nj] = (uint32_t)(FA_BY + FB_BY + (wn * 32 + nj * 16 + frow) * 128);
    }

    float ag[4][4][4], au[4][4][4];
    #pragma unroll
    for (int mi = 0; mi < 4; mi++)
        #pragma unroll
        for (int j = 0; j < 4; j++)
            #pragma unroll
            for (int r = 0; r < 4; r++) { ag[mi][j][r] = 0.0f; au[mi][j][r] = 0.0f; }

    issue(0); CP_COMMIT;
    issue(1); CP_COMMIT;

    for (int kb = 0; kb < nkb; ++kb) {
        if (kb + 1 < nkb) CP_WAIT(1); else CP_WAIT(0);
        __syncthreads();
        if (kb + 2 < nkb) { issue(kb + 2); CP_COMMIT; }

        const uint32_t base = sb + (kb % NSTAGE) * STAGE_F;
        #pragma unroll
        for (int ks = 0; ks < 4; ks++) {
            const uint32_t colx = (uint32_t)(((2 * ks + fg) ^ fx) << 4);
            uint32_t a[4][4], bg[2][4], bu[2][4];
            #pragma unroll
            for (int mi = 0; mi < 4; mi++) ldsm_x4(a[mi], base + arow[mi] + colx);
            #pragma unroll
            for (int nj = 0; nj < 2; nj++) {
                ldsm_x4(bg[nj], base + grow[nj] + colx);
                ldsm_x4(bu[nj], base + urow[nj] + colx);
            }
            #pragma unroll
            for (int mi = 0; mi < 4; mi++)
                #pragma unroll
                for (int nj = 0; nj < 2; nj++) {
                    mma16816(ag[mi][2 * nj + 0], a[mi], bg[nj][0], bg[nj][2]);
                    mma16816(ag[mi][2 * nj + 1], a[mi], bg[nj][1], bg[nj][3]);
                    mma16816(au[mi][2 * nj + 0], a[mi], bu[nj][0], bu[nj][2]);
                    mma16816(au[mi][2 * nj + 1], a[mi], bu[nj][1], bu[nj][3]);
                }
        }
    }

    const int rb = m0 + wm * 64 + (lane >> 2);
    const int cb = n0 + wn * 32 + (lane & 3) * 2;
    #pragma unroll
    for (int mi = 0; mi < 4; mi++) {
        #pragma unroll
        for (int j = 0; j < 4; j++) {
            const int r0 = rb + mi * 16;
            const int c  = cb + j * 8;
            float g0 = ag[mi][j][0], g1 = ag[mi][j][1], g2 = ag[mi][j][2], g3 = ag[mi][j][3];
            float v0 = g0 / (1.0f + __expf(-g0)) * au[mi][j][0];
            float v1 = g1 / (1.0f + __expf(-g1)) * au[mi][j][1];
            float v2 = g2 / (1.0f + __expf(-g2)) * au[mi][j][2];
            float v3 = g3 / (1.0f + __expf(-g3)) * au[mi][j][3];
            *(__half2*)(act + (size_t)r0 * INTP + c)       = __floats2half2_rn(v0, v1);
            *(__half2*)(act + (size_t)(r0 + 8) * INTP + c) = __floats2half2_rn(v2, v3);
        }
    }
}

// ---------------- fp32 -> fp16 weight convert with padding ----------------
__global__ void cvt_pad(const float* __restrict__ in, __half* __restrict__ out,
                        int ro, int co, int ri, int ci) {
    const size_t i = (size_t)blockIdx.x * blockDim.x + threadIdx.x;
    const size_t n4 = ((size_t)ro * co) >> 2;
    if (i >= n4) return;
    const int cw = co >> 2;
    const int r = (int)(i / cw);
    const int c = (int)(i - (size_t)r * cw) * 4;
    __half2 h0 = __floats2half2_rn(0.f, 0.f), h1 = h0;
    if (r < ri && c < ci) {
        float4 v = *(const float4*)(in + (size_t)r * ci + c);
        h0 = __floats2half2_rn(v.x, v.y);
        h1 = __floats2half2_rn(v.z, v.w);
    }
    __half2* d = (__half2*)(out + (size_t)r * co + c);
    d[0] = h0; d[1] = h1;
}

// ---------------- rmsnorm -> fp16 ----------------
__global__ void rmsnorm_h(const float* __restrict__ x, const float* __restrict__ w,
                          __half* __restrict__ out) {
    const int row = blockIdx.x, t = threadIdx.x;
    const float4* xv = (const float4*)(x + (size_t)row * HID);
    const float4* wv = (const float4*)w;
    float4 a = xv[t], b = xv[t + 256];
    float ss = a.x*a.x + a.y*a.y + a.z*a.z + a.w*a.w
             + b.x*b.x + b.y*b.y + b.z*b.z + b.w*b.w;
    __shared__ float red[8];
    #pragma unroll
    for (int o = 16; o; o >>= 1) ss += __shfl_xor_sync(0xffffffffu, ss, o);
    if ((t & 31) == 0) red[t >> 5] = ss;
    __syncthreads();
    float tot = red[0]+red[1]+red[2]+red[3]+red[4]+red[5]+red[6]+red[7];
    const float sc = rsqrtf(tot * (1.0f / HID) + EPS);
    float4 wa = wv[t], wb = wv[t + 256];
    __half2* ov = (__half2*)(out + (size_t)row * HID);
    ov[2*t]   = __floats2half2_rn(a.x*sc*wa.x, a.y*sc*wa.y);
    ov[2*t+1] = __floats2half2_rn(a.z*sc*wa.z, a.w*sc*wa.w);
    ov[2*(t+256)]   = __floats2half2_rn(b.x*sc*wb.x, b.y*sc*wb.y);
    ov[2*(t+256)+1] = __floats2half2_rn(b.z*sc*wb.z, b.w*sc*wb.w);
}

// ---------------- launcher ----------------
extern "C" void kernel_launch(void* const* d_in, const int* in_sizes, int n_in,
                              void* d_out, int out_size) {
    const float* x      = (const float*)d_in[0];
    const float* in_w   = (const float*)d_in[2];
    const float* post_w = (const float*)d_in[3];
    const float* Wq     = (const float*)d_in[4];
    const float* Wo     = (const float*)d_in[5];
    const float* Wg     = (const float*)d_in[6];
    const float* Wu     = (const float*)d_in[7];
    const float* Wd     = (const float*)d_in[8];
    float* out = (float*)d_out;
    const int T = in_sizes[0] / HID;  // 4096

    __half *xn, *q, *act, *wq, *wo, *wg, *wu, *wd;
    float* hidden;
    cudaGetSymbolAddress((void**)&xn, g_xn);
    cudaGetSymbolAddress((void**)&q, g_q);
    cudaGetSymbolAddress((void**)&hidden, g_hidden);
    cudaGetSymbolAddress((void**)&act, g_act);
    cudaGetSymbolAddress((void**)&wq, g_wq);
    cudaGetSymbolAddress((void**)&wo, g_wo);
    cudaGetSymbolAddress((void**)&wg, g_wg);
    cudaGetSymbolAddress((void**)&wu, g_wu);
    cudaGetSymbolAddress((void**)&wd, g_wd);

    cudaFuncSetAttribute(gemm_qod<0>, cudaFuncAttributeMaxDynamicSharedMemorySize, SMEM_A);
    cudaFuncSetAttribute(gemm_qod<1>, cudaFuncAttributeMaxDynamicSharedMemorySize, SMEM_A);
    cudaFuncSetAttribute(gemm_gateup, cudaFuncAttributeMaxDynamicSharedMemorySize, SMEM_F);

    // weight conversion (fp32 -> fp16, padded for INTER)
    {
        auto launch_cvt = [&](const float* src, __half* dst, int ro, int co, int ri, int ci) {
            size_t n4 = ((size_t)ro * co) >> 2;
            cvt_pad<<<(unsigned)((n4 + 255) / 256), 256>>>(src, dst, ro, co, ri, ci);
        };
        launch_cvt(Wq, wq, HID, HID, HID, HID);
        launch_cvt(Wo, wo, HID, HID, HID, HID);
        launch_cvt(Wg, wg, INTP, HID, INTER, HID);
        launch_cvt(Wu, wu, INTP, HID, INTER, HID);
        launch_cvt(Wd, wd, HID, INTP, HID, INTER);
    }

    const dim3 gridH(T / 128, HID / 128);    // (32, 16)
    const dim3 gridF(T / 128, INTP / 64);    // (32, 172)

    // 1. input_layernorm -> fp16
    rmsnorm_h<<<T, 256>>>(x, in_w, xn);
    // 2. q = xn @ Wq^T (fp16)
    gemm_qod<0><<<gridH, 128, SMEM_A>>>(xn, wq, nullptr, q, nullptr, HID, HID);
    // 3. hidden = x + q @ Wo^T (fp32)
    gemm_qod<1><<<gridH, 128, SMEM_A>>>(q, wo, x, nullptr, hidden, HID, HID);
    // 4. post_attention_layernorm -> fp16
    rmsnorm_h<<<T, 256>>>(hidden, post_w, xn);
    // 5. act = silu(xn@Wg^T) * (xn@Wu^T)   (fused, fp16, padded N)
    gemm_gateup<<<gridF, 128, SMEM_F>>>(xn, wg, wu, act, HID);
    // 6. out = hidden + act @ Wd^T (fp32)
    gemm_qod<1><<<gridH, 128, SMEM_A>>>(act, wd, hidden, nullptr, out, INTP, HID);
}

// round 12
// speedup vs baseline: 1.0861x; 1.0169x over previous
#include <cuda_runtime.h>
#include <cuda_fp16.h>
#include <cstdint>

#define HID   2048
#define INTER 10944
#define INTP  11008          // padded: 86*128, 172*64
#define TTOK  4096
#define EPS   1e-6f

#define BK 64                // fp16 elems per k-chunk = 128B swizzled row
#define NSTAGE 2

// ---- kernel A (q/o/down): BM=128, BN=128, 128 threads (2x2 warps, 64x64 tiles) ----
#define A_BY   (128*128)                 // 16 KB
#define B_BY   (128*128)                 // 16 KB
#define STAGE_A (A_BY + B_BY)            // 32 KB
#define SMEM_A (NSTAGE*STAGE_A)          // 64 KB -> 3 CTAs/SM

// ---- kernel B (fused gate/up): BM=128, BN=64 per weight ----
#define FA_BY  (128*128)                 // 16 KB
#define FB_BY  (64*128)                  // 8 KB each weight
#define STAGE_F (FA_BY + 2*FB_BY)        // 32 KB
#define SMEM_F (NSTAGE*STAGE_F)          // 64 KB -> 3 CTAs/SM

// ---------------- scratch ----------------
__device__ __half g_xn[(size_t)TTOK * HID];
__device__ __half g_q[(size_t)TTOK * HID];
__device__ float  g_hidden[(size_t)TTOK * HID];
__device__ __half g_act[(size_t)TTOK * INTP];
__device__ __half g_wq[(size_t)HID * HID];
__device__ __half g_wo[(size_t)HID * HID];
__device__ __half g_wg[(size_t)INTP * HID];
__device__ __half g_wu[(size_t)INTP * HID];
__device__ __half g_wd[(size_t)HID * INTP];

// ---------------- PTX helpers ----------------
__device__ __forceinline__ uint32_t smem_u32(const void* p) {
    uint32_t a;
    asm("{ .reg .u64 t; cvta.to.shared.u64 t, %1; cvt.u32.u64 %0, t; }" : "=r"(a) : "l"(p));
    return a;
}
#define SWZ(off) ((off) ^ (((off) >> 3) & 0x70))

__device__ __forceinline__ void cp16(uint32_t smem_dst, const void* gsrc) {
    asm volatile("cp.async.cg.shared.global [%0], [%1], 16;" :: "r"(smem_dst), "l"(gsrc));
}
#define CP_COMMIT  asm volatile("cp.async.commit_group;" ::: "memory")
#define CP_WAIT(n) asm volatile("cp.async.wait_group %0;" :: "n"(n) : "memory")

__device__ __forceinline__ void ldsm_x4(uint32_t r[4], uint32_t saddr) {
    asm volatile("ldmatrix.sync.aligned.m8n8.x4.shared.b16 {%0,%1,%2,%3}, [%4];"
        : "=r"(r[0]), "=r"(r[1]), "=r"(r[2]), "=r"(r[3]) : "r"(saddr));
}

__device__ __forceinline__ void mma16816(float c[4], const uint32_t a[4],
                                         uint32_t b0, uint32_t b1) {
    asm volatile(
        "mma.sync.aligned.m16n8k16.row.col.f32.f16.f16.f32 "
        "{%0,%1,%2,%3}, {%4,%5,%6,%7}, {%8,%9}, {%0,%1,%2,%3};"
        : "+f"(c[0]), "+f"(c[1]), "+f"(c[2]), "+f"(c[3])
        : "r"(a[0]), "r"(a[1]), "r"(a[2]), "r"(a[3]), "r"(b0), "r"(b1));
}

// ================= kernel A: C[M,N] = A[M,K] @ B[N,K]^T =================
// 128 threads, warps 2(M) x 2(N), warp tile 64x64, 3 CTAs/SM.
// EPI 0: fp16 -> Ch.   EPI 1: fp32 acc + Res -> Cf.
template <int EPI>
__global__ void __launch_bounds__(128, 3)
gemm_qod(const __half* __restrict__ A, const __half* __restrict__ B,
         const float* __restrict__ Res, __half* __restrict__ Ch,
         float* __restrict__ Cf, int K, int N) {
    extern __shared__ char smem[];
    const uint32_t sb = smem_u32(smem);
    const int tid = threadIdx.x, warp = tid >> 5, lane = tid & 31;
    const int wm = warp & 1, wn = warp >> 1;
    const int m0 = blockIdx.x * 128, n0 = blockIdx.y * 128;
    const int nkb = K / BK;

    const __half* Ag = A + (size_t)m0 * K;
    const __half* Bg = B + (size_t)n0 * K;
    auto issue = [&](int kb) {
        const uint32_t base = sb + (kb & 1) * STAGE_A;
        const int koff = kb * BK;
        #pragma unroll
        for (int i = 0; i < 16; i++) {
            const int c = tid + i * 128;
            const int idx = c & 1023, r = idx >> 3, cc = idx & 7;
            const uint32_t so = SWZ((uint32_t)(r * 128 + cc * 16));
            const size_t go = (size_t)r * K + koff + cc * 8;
            if (c < 1024) cp16(base + so,         Ag + go);
            else          cp16(base + A_BY + so,  Bg + go);
        }
    };

    const int frow = (lane & 7) | (((lane >> 3) & 1) << 3);
    const int fg = lane >> 4, fx = frow & 7;
    uint32_t arow[4], brow[4];
    #pragma unroll
    for (int mi = 0; mi < 4; mi++) arow[mi] = (uint32_t)((wm * 64 + mi * 16 + frow) * 128);
    #pragma unroll
    for (int nj = 0; nj < 4; nj++) brow[nj] = (uint32_t)(A_BY + (wn * 64 + nj * 16 + frow) * 128);

    float acc[4][8][4];
    #pragma unroll
    for (int mi = 0; mi < 4; mi++)
        #pragma unroll
        for (int j = 0; j < 8; j++)
            #pragma unroll
            for (int r = 0; r < 4; r++) acc[mi][j][r] = 0.0f;

    issue(0); CP_COMMIT;

    for (int kb = 0; kb < nkb; ++kb) {
        if (kb + 1 < nkb) { issue(kb + 1); CP_COMMIT; CP_WAIT(1); }
        else              { CP_WAIT(0); }
        __syncthreads();

        const uint32_t base = sb + (kb & 1) * STAGE_A;
        #pragma unroll
        for (int ks = 0; ks < 4; ks++) {
            const uint32_t colx = (uint32_t)(((2 * ks + fg) ^ fx) << 4);
            uint32_t a[4][4], b[4][4];
            #pragma unroll
            for (int mi = 0; mi < 4; mi++) ldsm_x4(a[mi], base + arow[mi] + colx);
            #pragma unroll
            for (int nj = 0; nj < 4; nj++) ldsm_x4(b[nj], base + brow[nj] + colx);
            #pragma unroll
            for (int mi = 0; mi < 4; mi++)
                #pragma unroll
                for (int nj = 0; nj < 4; nj++) {
                    mma16816(acc[mi][2 * nj + 0], a[mi], b[nj][0], b[nj][2]);
                    mma16816(acc[mi][2 * nj + 1], a[mi], b[nj][1], b[nj][3]);
                }
        }
        __syncthreads();   // 2-stage ring: stage (kb+1)&1 gets overwritten next iter
    }

    const int rb = m0 + wm * 64 + (lane >> 2);
    const int cb = n0 + wn * 64 + (lane & 3) * 2;
    #pragma unroll
    for (int mi = 0; mi < 4; mi++) {
        #pragma unroll
        for (int j = 0; j < 8; j++) {
            const int r0 = rb + mi * 16;
            const int c  = cb + j * 8;
            if (EPI == 0) {
                *(__half2*)(Ch + (size_t)r0 * N + c) =
                    __floats2half2_rn(acc[mi][j][0], acc[mi][j][1]);
                *(__half2*)(Ch + (size_t)(r0 + 8) * N + c) =
                    __floats2half2_rn(acc[mi][j][2], acc[mi][j][3]);
            } else {
                float2 v0 = *(const float2*)(Res + (size_t)r0 * N + c);
                float2 v1 = *(const float2*)(Res + (size_t)(r0 + 8) * N + c);
                v0.x += acc[mi][j][0]; v0.y += acc[mi][j][1];
                v1.x += acc[mi][j][2]; v1.y += acc[mi][j][3];
                *(float2*)(Cf + (size_t)r0 * N + c)       = v0;
                *(float2*)(Cf + (size_t)(r0 + 8) * N + c) = v1;
            }
        }
    }
}

// ======= kernel B: fused gate/up + silu.  act = silu(A@Wg^T) * (A@Wu^T) =======
// 128 threads, warps 2x2, BN=64 per weight, warp tile 64x32 per weight, 3 CTAs/SM.
__global__ void __launch_bounds__(128, 3)
gemm_gateup(const __half* __restrict__ A, const __half* __restrict__ Wg,
            const __half* __restrict__ Wu, __half* __restrict__ act, int K) {
    extern __shared__ char smem[];
    const uint32_t sb = smem_u32(smem);
    const int tid = threadIdx.x, warp = tid >> 5, lane = tid & 31;
    const int wm = warp & 1, wn = warp >> 1;
    const int m0 = blockIdx.x * 128, n0 = blockIdx.y * 64;
    const int nkb = K / BK;

    const __half* Ag = A  + (size_t)m0 * K;
    const __half* Gg = Wg + (size_t)n0 * K;
    const __half* Ug = Wu + (size_t)n0 * K;
    auto issue = [&](int kb) {
        const uint32_t base = sb + (kb & 1) * STAGE_F;
        const int koff = kb * BK;
        #pragma unroll
        for (int i = 0; i < 16; i++) {
            const int c = tid + i * 128;
            if (c < 1024) {
                const int r = c >> 3, cc = c & 7;
                cp16(base + SWZ((uint32_t)(r * 128 + cc * 16)),
                     Ag + (size_t)r * K + koff + cc * 8);
            } else if (c < 1536) {
                const int idx = c - 1024, r = idx >> 3, cc = idx & 7;
                cp16(base + FA_BY + SWZ((uint32_t)(r * 128 + cc * 16)),
                     Gg + (size_t)r * K + koff + cc * 8);
            } else {
                const int idx = c - 1536, r = idx >> 3, cc = idx & 7;
                cp16(base + FA_BY + FB_BY + SWZ((uint32_t)(r * 128 + cc * 16)),
                     Ug + (size_t)r * K + koff + cc * 8);
            }
        }
    };

    const int frow = (lane & 7) | (((lane >> 3) & 1) << 3);
    const int fg = lane >> 4, fx = frow & 7;
    uint32_t arow[4], grow[2], urow[2];
    #pragma unroll
    for (int mi = 0; mi < 4; mi++) arow[mi] = (uint32_t)((wm * 64 + mi * 16 + frow) * 128);
    #pragma unroll
    for (int nj = 0; nj < 2; nj++) {
        grow[nj] = (uint32_t)(FA_BY         + (wn * 32 + nj * 16 + frow) * 128);
        urow[nj] = (uint32_t)(FA_BY + FB_BY + (wn * 32 + nj * 16 + frow) * 128);
    }

    float ag[4][4][4], au[4][4][4];
    #pragma unroll
    for (int mi = 0; mi < 4; mi++)
        #pragma unroll
        for (int j = 0; j < 4; j++)
            #pragma unroll
            for (int r = 0; r < 4; r++) { ag[mi][j][r] = 0.0f; au[mi][j][r] = 0.0f; }

    issue(0); CP_COMMIT;

    for (int kb = 0; kb < nkb; ++kb) {
        if (kb + 1 < nkb) { issue(kb + 1); CP_COMMIT; CP_WAIT(1); }
        else              { CP_WAIT(0); }
        __syncthreads();

        const uint32_t base = sb + (kb & 1) * STAGE_F;
        #pragma unroll
        for (int ks = 0; ks < 4; ks++) {
            const uint32_t colx = (uint32_t)(((2 * ks + fg) ^ fx) << 4);
            uint32_t a[4][4], bg[2][4], bu[2][4];
            #pragma unroll
            for (int mi = 0; mi < 4; mi++) ldsm_x4(a[mi], base + arow[mi] + colx);
            #pragma unroll
            for (int nj = 0; nj < 2; nj++) {
                ldsm_x4(bg[nj], base + grow[nj] + colx);
                ldsm_x4(bu[nj], base + urow[nj] + colx);
            }
            #pragma unroll
            for (int mi = 0; mi < 4; mi++)
                #pragma unroll
                for (int nj = 0; nj < 2; nj++) {
                    mma16816(ag[mi][2 * nj + 0], a[mi], bg[nj][0], bg[nj][2]);
                    mma16816(ag[mi][2 * nj + 1], a[mi], bg[nj][1], bg[nj][3]);
                    mma16816(au[mi][2 * nj + 0], a[mi], bu[nj][0], bu[nj][2]);
                    mma16816(au[mi][2 * nj + 1], a[mi], bu[nj][1], bu[nj][3]);
                }
        }
        __syncthreads();
    }

    const int rb = m0 + wm * 64 + (lane >> 2);
    const int cb = n0 + wn * 32 + (lane & 3) * 2;
    #pragma unroll
    for (int mi = 0; mi < 4; mi++) {
        #pragma unroll
        for (int j = 0; j < 4; j++) {
            const int r0 = rb + mi * 16;
            const int c  = cb + j * 8;
            float g0 = ag[mi][j][0], g1 = ag[mi][j][1], g2 = ag[mi][j][2], g3 = ag[mi][j][3];
            float v0 = g0 / (1.0f + __expf(-g0)) * au[mi][j][0];
            float v1 = g1 / (1.0f + __expf(-g1)) * au[mi][j][1];
            float v2 = g2 / (1.0f + __expf(-g2)) * au[mi][j][2];
            float v3 = g3 / (1.0f + __expf(-g3)) * au[mi][j][3];
            *(__half2*)(act + (size_t)r0 * INTP + c)       = __floats2half2_rn(v0, v1);
            *(__half2*)(act + (size_t)(r0 + 8) * INTP + c) = __floats2half2_rn(v2, v3);
        }
    }
}

// ---------------- fp32 -> fp16 weight convert with padding ----------------
__global__ void cvt_pad(const float* __restrict__ in, __half* __restrict__ out,
                        int ro, int co, int ri, int ci) {
    const size_t i = (size_t)blockIdx.x * blockDim.x + threadIdx.x;
    const size_t n4 = ((size_t)ro * co) >> 2;
    if (i >= n4) return;
    const int cw = co >> 2;
    const int r = (int)(i / cw);
    const int c = (int)(i - (size_t)r * cw) * 4;
    __half2 h0 = __floats2half2_rn(0.f, 0.f), h1 = h0;
    if (r < ri && c < ci) {
        float4 v = *(const float4*)(in + (size_t)r * ci + c);
        h0 = __floats2half2_rn(v.x, v.y);
        h1 = __floats2half2_rn(v.z, v.w);
    }
    __half2* d = (__half2*)(out + (size_t)r * co + c);
    d[0] = h0; d[1] = h1;
}

// ---------------- rmsnorm -> fp16 ----------------
__global__ void rmsnorm_h(const float* __restrict__ x, const float* __restrict__ w,
                          __half* __restrict__ out) {
    const int row = blockIdx.x, t = threadIdx.x;
    const float4* xv = (const float4*)(x + (size_t)row * HID);
    const float4* wv = (const float4*)w;
    float4 a = xv[t], b = xv[t + 256];
    float ss = a.x*a.x + a.y*a.y + a.z*a.z + a.w*a.w
             + b.x*b.x + b.y*b.y + b.z*b.z + b.w*b.w;
    __shared__ float red[8];
    #pragma unroll
    for (int o = 16; o; o >>= 1) ss += __shfl_xor_sync(0xffffffffu, ss, o);
    if ((t & 31) == 0) red[t >> 5] = ss;
    __syncthreads();
    float tot = red[0]+red[1]+red[2]+red[3]+red[4]+red[5]+red[6]+red[7];
    const float sc = rsqrtf(tot * (1.0f / HID) + EPS);
    float4 wa = wv[t], wb = wv[t + 256];
    __half2* ov = (__half2*)(out + (size_t)row * HID);
    ov[2*t]   = __floats2half2_rn(a.x*sc*wa.x, a.y*sc*wa.y);
    ov[2*t+1] = __floats2half2_rn(a.z*sc*wa.z, a.w*sc*wa.w);
    ov[2*(t+256)]   = __floats2half2_rn(b.x*sc*wb.x, b.y*sc*wb.y);
    ov[2*(t+256)+1] = __floats2half2_rn(b.z*sc*wb.z, b.w*sc*wb.w);
}

// ---------------- launcher ----------------
extern "C" void kernel_launch(void* const* d_in, const int* in_sizes, int n_in,
                              void* d_out, int out_size) {
    const float* x      = (const float*)d_in[0];
    const float* in_w   = (const float*)d_in[2];
    const float* post_w = (const float*)d_in[3];
    const float* Wq     = (const float*)d_in[4];
    const float* Wo     = (const float*)d_in[5];
    const float* Wg     = (const float*)d_in[6];
    const float* Wu     = (const float*)d_in[7];
    const float* Wd     = (const float*)d_in[8];
    float* out = (float*)d_out;
    const int T = in_sizes[0] / HID;  // 4096

    __half *xn, *q, *act, *wq, *wo, *wg, *wu, *wd;
    float* hidden;
    cudaGetSymbolAddress((void**)&xn, g_xn);
    cudaGetSymbolAddress((void**)&q, g_q);
    cudaGetSymbolAddress((void**)&hidden, g_hidden);
    cudaGetSymbolAddress((void**)&act, g_act);
    cudaGetSymbolAddress((void**)&wq, g_wq);
    cudaGetSymbolAddress((void**)&wo, g_wo);
    cudaGetSymbolAddress((void**)&wg, g_wg);
    cudaGetSymbolAddress((void**)&wu, g_wu);
    cudaGetSymbolAddress((void**)&wd, g_wd);

    cudaFuncSetAttribute(gemm_qod<0>, cudaFuncAttributeMaxDynamicSharedMemorySize, SMEM_A);
    cudaFuncSetAttribute(gemm_qod<1>, cudaFuncAttributeMaxDynamicSharedMemorySize, SMEM_A);
    cudaFuncSetAttribute(gemm_gateup, cudaFuncAttributeMaxDynamicSharedMemorySize, SMEM_F);

    // weight conversion (fp32 -> fp16, padded for INTER)
    {
        auto launch_cvt = [&](const float* src, __half* dst, int ro, int co, int ri, int ci) {
            size_t n4 = ((size_t)ro * co) >> 2;
            cvt_pad<<<(unsigned)((n4 + 255) / 256), 256>>>(src, dst, ro, co, ri, ci);
        };
        launch_cvt(Wq, wq, HID, HID, HID, HID);
        launch_cvt(Wo, wo, HID, HID, HID, HID);
        launch_cvt(Wg, wg, INTP, HID, INTER, HID);
        launch_cvt(Wu, wu, INTP, HID, INTER, HID);
        launch_cvt(Wd, wd, HID, INTP, HID, INTER);
    }

    const dim3 gridH(T / 128, HID / 128);    // (32, 16)
    const dim3 gridF(T / 128, INTP / 64);    // (32, 172)

    // 1. input_layernorm -> fp16
    rmsnorm_h<<<T, 256>>>(x, in_w, xn);
    // 2. q = xn @ Wq^T (fp16)
    gemm_qod<0><<<gridH, 128, SMEM_A>>>(xn, wq, nullptr, q, nullptr, HID, HID);
    // 3. hidden = x + q @ Wo^T (fp32)
    gemm_qod<1><<<gridH, 128, SMEM_A>>>(q, wo, x, nullptr, hidden, HID, HID);
    // 4. post_attention_layernorm -> fp16
    rmsnorm_h<<<T, 256>>>(hidden, post_w, xn);
    // 5. act = silu(xn@Wg^T) * (xn@Wu^T)   (fused, fp16, padded N)
    gemm_gateup<<<gridF, 128, SMEM_F>>>(xn, wg, wu, act, HID);
    // 6. out = hidden + act @ Wd^T (fp32)
    gemm_qod<1><<<gridH, 128, SMEM_A>>>(act, wd, hidden, nullptr, out, INTP, HID);
}